// round 12
// baseline (speedup 1.0000x reference)
#include <cuda_runtime.h>
#include <cuda_fp16.h>
#include <cstdint>

// Problem constants
#define B_    16
#define T_    64
#define C_    512
#define S_    4096
#define INNER 512
#define DIMH  64
#define NHEAD 8
#define BH_   (B_ * NHEAD)
#define SPLIT 4
#define S_PER (S_ / SPLIT)      // 1024

// Scratch (device globals; no allocations allowed)
__device__ float    g_q    [B_ * T_ * INNER];             // q projection f32
__device__ float    g_ao   [B_ * T_ * INNER];             // attention out f32
__device__ __half   g_w16  [2 * INNER * C_];              // concat(Wk,Wv) fp16
__device__ __half   g_lang16[B_ * T_ * C_];               // lang fp16 [1024][512]
__device__ __half   g_ao16 [B_ * T_ * INNER];             // attention out fp16
__device__ uint32_t g_wqT  [(C_ / 2) * INNER];            // Wq^T pair-packed [256][512]
__device__ uint32_t g_woT  [(INNER / 2) * C_];            // Wo^T pair-packed [256][512]
__device__ uint32_t g_v16p [(long)B_ * (C_ / 2) * S_];    // vis fp16 pair-packed
__device__ __half   g_q16  [BH_ * T_ * DIMH];             // q fp16 (bh,t,d), pre-scaled
__device__ __half   g_k16  [(long)BH_ * S_ * DIMH];       // K fp16 s-major (bh,s,d)
__device__ __half   g_v16  [(long)BH_ * DIMH * S_];       // V fp16 d-major (bh,d,s)
__device__ float    g_op   [(long)SPLIT * BH_ * T_ * DIMH]; // partial O
__device__ float    g_ml   [SPLIT * BH_ * T_ * 2];        // partial (m,l)

// pack two fp32 -> one .f16x2 register (lo = first arg)
__device__ __forceinline__ uint32_t f2h2(float lo, float hi) {
    uint32_t r;
    asm("cvt.rn.f16x2.f32 %0, %1, %2;" : "=r"(r) : "f"(hi), "f"(lo));
    return r;
}

__device__ __forceinline__ uint32_t smem_u32(const void* p) {
    uint32_t a;
    asm("{ .reg .u64 t; cvta.to.shared.u64 t, %1; cvt.u32.u64 %0, t; }" : "=r"(a) : "l"(p));
    return a;
}

// ---------------------------------------------------------------------------
__global__ void conv16(const float* __restrict__ src, __half* __restrict__ dst)
{
    const int i = blockIdx.x * 256 + threadIdx.x;
    dst[i] = __float2half_rn(src[i]);
}

// fused prep: w16 concat (blocks 0..1023), Wq^T pack (1024..1535),
// Wo^T pack (1536..2047), lang conv (2048..4095)
__global__ void prep_all(const float* __restrict__ Wk, const float* __restrict__ Wv,
                         const float* __restrict__ Wq, const float* __restrict__ Wo,
                         const float* __restrict__ lang,
                         __half* __restrict__ w16, uint32_t* __restrict__ wqT,
                         uint32_t* __restrict__ woT, __half* __restrict__ lang16)
{
    const int blk = blockIdx.x;
    if (blk < 1024) {
        const int i = blk * 256 + threadIdx.x;
        w16[i]              = __float2half_rn(Wk[i]);
        w16[INNER * C_ + i] = __float2half_rn(Wv[i]);
    } else if (blk < 1536) {
        const int idx = (blk - 1024) * 256 + threadIdx.x;   // k2*512 + n
        const int n  = idx & 511;
        const int k2 = idx >> 9;
        const float* s = Wq + n * 512 + 2 * k2;
        wqT[idx] = f2h2(s[0], s[1]);
    } else if (blk < 2048) {
        const int idx = (blk - 1536) * 256 + threadIdx.x;
        const int n  = idx & 511;
        const int k2 = idx >> 9;
        const float* s = Wo + n * 512 + 2 * k2;
        woT[idx] = f2h2(s[0], s[1]);
    } else {
        const int i = (blk - 2048) * 256 + threadIdx.x;
        lang16[i] = __float2half_rn(lang[i]);
    }
}

__global__ void prep_vis16(const float* __restrict__ vis, uint32_t* __restrict__ vp)
{
    const long i  = (long)blockIdx.x * 256 + threadIdx.x;
    const long s  = i & (S_ - 1);
    const long c2 = (i >> 12) & 255;
    const long b  = i >> 20;
    const float* src = vis + (((b * C_) + 2 * c2) << 12) + s;
    vp[i] = f2h2(src[0], src[S_]);
}

// q f32 (B,T,inner) -> q16 (bh,t,d), scaled by 0.125   [validated]
__global__ void prep_q16(const float* __restrict__ q, __half* __restrict__ q16)
{
    const int i = blockIdx.x * 256 + threadIdx.x;   // 0 .. 524287
    const int d = i & 63;
    const int h = (i >> 6) & 7;
    const int t = (i >> 9) & 63;
    const int b = i >> 15;
    q16[(((b * 8 + h) * T_) + t) * DIMH + d] = __float2half_rn(q[i] * 0.125f);
}

// ---------------------------------------------------------------------------
// shared tile sizes (kv kernel + its clone)
#define NSTAGE   4
#define A_ST_U32 (128 * 20)
#define B_ST_U32 (16 * 136)
#define KV_SMEM  (NSTAGE * (A_ST_U32 + B_ST_U32) * 4)   // 75776 bytes

// ---------------------------------------------------------------------------
// Projection GEMM: Cf[1024][512] = A16[1024][512] @ (packed B)[512][512]
// Verbatim clone of gemm_kv_f16 mainloop with N=512 and f32 epilogue.  [validated]
// ---------------------------------------------------------------------------
__global__ __launch_bounds__(256)
void gemm_proj(const __half* __restrict__ A16,      // [1024][512]
               const uint32_t* __restrict__ Bp,     // [256][512] pairs k2-major
               float* __restrict__ Cf)              // [1024][512]
{
    extern __shared__ uint32_t smdyn[];
    uint32_t (*As)[128][20]  = (uint32_t(*)[128][20])smdyn;
    uint32_t (*Bs)[16][136]  = (uint32_t(*)[16][136])(smdyn + NSTAGE * A_ST_U32);

    const int m0 = blockIdx.y * 128;
    const int n0 = blockIdx.x * 128;
    const uint32_t* Ap = (const uint32_t*)A16;               // pair view [1024][256]

    const int tid  = threadIdx.x;
    const int warp = tid >> 5;
    const int lane = tid & 31;
    const int wm   = (warp >> 1) * 32;
    const int wn   = (warp & 1) * 64;
    const int g    = lane >> 2;
    const int tg   = lane & 3;

    float acc[2][8][4];
    #pragma unroll
    for (int mt = 0; mt < 2; mt++)
        #pragma unroll
        for (int nt = 0; nt < 8; nt++)
            #pragma unroll
            for (int i = 0; i < 4; i++)
                acc[mt][nt][i] = 0.f;

    auto issue = [&](int ch, int st) {
        const int kc2 = ch * 16;
        #pragma unroll
        for (int t = 0; t < 2; t++) {
            const int idx = tid + t * 256;
            const int r = idx >> 2, p4 = (idx & 3) * 4;
            const uint32_t* src = &Ap[(long)(m0 + r) * (C_ / 2) + kc2 + p4];
            asm volatile("cp.async.cg.shared.global [%0], [%1], 16;"
                         :: "r"(smem_u32(&As[st][r][p4])), "l"(src));
        }
        #pragma unroll
        for (int t = 0; t < 2; t++) {
            const int idx = tid + t * 256;
            const int r = idx >> 5, c4 = (idx & 31) * 4;
            const uint32_t* src = &Bp[(long)(kc2 + r) * 512 + n0 + c4];
            asm volatile("cp.async.cg.shared.global [%0], [%1], 16;"
                         :: "r"(smem_u32(&Bs[st][r][c4])), "l"(src));
        }
        asm volatile("cp.async.commit_group;" ::: "memory");
    };

    issue(0, 0); issue(1, 1); issue(2, 2);

    const int NCH = C_ / 32;   // 16
    for (int ch = 0; ch < NCH; ++ch) {
        const int st = ch & (NSTAGE - 1);
        asm volatile("cp.async.wait_group 2;" ::: "memory");
        __syncthreads();

        #pragma unroll
        for (int ks = 0; ks < 2; ks++) {
            const int kb = ks * 8;
            uint32_t bf[8][2];
            #pragma unroll
            for (int nt = 0; nt < 8; nt++) {
                bf[nt][0] = Bs[st][kb + tg]    [wn + nt * 8 + g];
                bf[nt][1] = Bs[st][kb + tg + 4][wn + nt * 8 + g];
            }
            #pragma unroll
            for (int mt = 0; mt < 2; mt++) {
                const int mi = wm + mt * 16 + g;
                uint32_t a0 = As[st][mi]    [kb + tg];
                uint32_t a1 = As[st][mi + 8][kb + tg];
                uint32_t a2 = As[st][mi]    [kb + tg + 4];
                uint32_t a3 = As[st][mi + 8][kb + tg + 4];
                #pragma unroll
                for (int nt = 0; nt < 8; nt++) {
                    asm volatile(
                        "mma.sync.aligned.m16n8k16.row.col.f32.f16.f16.f32 "
                        "{%0,%1,%2,%3}, {%4,%5,%6,%7}, {%8,%9}, {%0,%1,%2,%3};"
                        : "+f"(acc[mt][nt][0]), "+f"(acc[mt][nt][1]),
                          "+f"(acc[mt][nt][2]), "+f"(acc[mt][nt][3])
                        : "r"(a0), "r"(a1), "r"(a2), "r"(a3),
                          "r"(bf[nt][0]), "r"(bf[nt][1]));
                }
            }
        }

        if (ch + NSTAGE - 1 < NCH)
            issue(ch + NSTAGE - 1, (ch + NSTAGE - 1) & (NSTAGE - 1));
    }

    #pragma unroll
    for (int mt = 0; mt < 2; mt++) {
        const int rA = m0 + wm + mt * 16 + g;
        const int rB = rA + 8;
        #pragma unroll
        for (int nt = 0; nt < 8; nt++) {
            const int col = n0 + wn + nt * 8 + 2 * tg;
            *(float2*)&Cf[(long)rA * 512 + col] = make_float2(acc[mt][nt][0], acc[mt][nt][1]);
            *(float2*)&Cf[(long)rB * 512 + col] = make_float2(acc[mt][nt][2], acc[mt][nt][3]);
        }
    }
}

// ---------------------------------------------------------------------------
// Fused k/v projection, fp16 mma, 4-stage cp.async (unchanged).  [validated]
// ---------------------------------------------------------------------------
__global__ __launch_bounds__(256)
void gemm_kv_f16(const __half* __restrict__ A16,      // [1024][512]
                 const uint32_t* __restrict__ Bp,     // [16][256][4096] pairs
                 __half* __restrict__ gk,             // (bh,s,d)
                 __half* __restrict__ gv)             // (bh,d,s)
{
    extern __shared__ uint32_t smdyn[];
    uint32_t (*As)[128][20]  = (uint32_t(*)[128][20])smdyn;
    uint32_t (*Bs)[16][136]  = (uint32_t(*)[16][136])(smdyn + NSTAGE * A_ST_U32);

    const int b  = blockIdx.z;
    const int m0 = blockIdx.y * 128;
    const int n0 = blockIdx.x * 128;
    const uint32_t* Ap = (const uint32_t*)A16;
    const uint32_t* Bb = Bp + (long)b * (C_ / 2) * S_;

    const int tid  = threadIdx.x;
    const int warp = tid >> 5;
    const int lane = tid & 31;
    const int wm   = (warp >> 1) * 32;
    const int wn   = (warp & 1) * 64;
    const int g    = lane >> 2;
    const int tg   = lane & 3;

    float acc[2][8][4];
    #pragma unroll
    for (int mt = 0; mt < 2; mt++)
        #pragma unroll
        for (int nt = 0; nt < 8; nt++)
            #pragma unroll
            for (int i = 0; i < 4; i++)
                acc[mt][nt][i] = 0.f;

    auto issue = [&](int ch, int st) {
        const int kc2 = ch * 16;
        #pragma unroll
        for (int t = 0; t < 2; t++) {
            const int idx = tid + t * 256;
            const int r = idx >> 2, p4 = (idx & 3) * 4;
            const uint32_t* src = &Ap[(long)(m0 + r) * (C_ / 2) + kc2 + p4];
            asm volatile("cp.async.cg.shared.global [%0], [%1], 16;"
                         :: "r"(smem_u32(&As[st][r][p4])), "l"(src));
        }
        #pragma unroll
        for (int t = 0; t < 2; t++) {
            const int idx = tid + t * 256;
            const int r = idx >> 5, c4 = (idx & 31) * 4;
            const uint32_t* src = &Bb[(long)(kc2 + r) * S_ + n0 + c4];
            asm volatile("cp.async.cg.shared.global [%0], [%1], 16;"
                         :: "r"(smem_u32(&Bs[st][r][c4])), "l"(src));
        }
        asm volatile("cp.async.commit_group;" ::: "memory");
    };

    issue(0, 0); issue(1, 1); issue(2, 2);

    const int NCH = C_ / 32;   // 16
    for (int ch = 0; ch < NCH; ++ch) {
        const int st = ch & (NSTAGE - 1);
        asm volatile("cp.async.wait_group 2;" ::: "memory");
        __syncthreads();

        #pragma unroll
        for (int ks = 0; ks < 2; ks++) {
            const int kb = ks * 8;
            uint32_t bf[8][2];
            #pragma unroll
            for (int nt = 0; nt < 8; nt++) {
                bf[nt][0] = Bs[st][kb + tg]    [wn + nt * 8 + g];
                bf[nt][1] = Bs[st][kb + tg + 4][wn + nt * 8 + g];
            }
            #pragma unroll
            for (int mt = 0; mt < 2; mt++) {
                const int mi = wm + mt * 16 + g;
                uint32_t a0 = As[st][mi]    [kb + tg];
                uint32_t a1 = As[st][mi + 8][kb + tg];
                uint32_t a2 = As[st][mi]    [kb + tg + 4];
                uint32_t a3 = As[st][mi + 8][kb + tg + 4];
                #pragma unroll
                for (int nt = 0; nt < 8; nt++) {
                    asm volatile(
                        "mma.sync.aligned.m16n8k16.row.col.f32.f16.f16.f32 "
                        "{%0,%1,%2,%3}, {%4,%5,%6,%7}, {%8,%9}, {%0,%1,%2,%3};"
                        : "+f"(acc[mt][nt][0]), "+f"(acc[mt][nt][1]),
                          "+f"(acc[mt][nt][2]), "+f"(acc[mt][nt][3])
                        : "r"(a0), "r"(a1), "r"(a2), "r"(a3),
                          "r"(bf[nt][0]), "r"(bf[nt][1]));
                }
            }
        }

        if (ch + NSTAGE - 1 < NCH)
            issue(ch + NSTAGE - 1, (ch + NSTAGE - 1) & (NSTAGE - 1));
    }

    // epilogue: K rows (m<512) -> (bh,s,d) scalar halves; V rows -> (bh,d,s) half2
    #pragma unroll
    for (int mt = 0; mt < 2; mt++) {
        const int mA = m0 + wm + mt * 16 + g;
        const int mB = mA + 8;
        #pragma unroll
        for (int nt = 0; nt < 8; nt++) {
            const int col = n0 + wn + nt * 8 + 2 * tg;
            if (m0 < 512) {
                const int hA = mA >> 6, dA = mA & 63;
                const int hB = mB >> 6, dB = mB & 63;
                __half* pA = gk + ((long)(b * 8 + hA) * S_ + col) * DIMH + dA;
                __half* pB = gk + ((long)(b * 8 + hB) * S_ + col) * DIMH + dB;
                pA[0]    = __float2half_rn(acc[mt][nt][0]);
                pA[DIMH] = __float2half_rn(acc[mt][nt][1]);
                pB[0]    = __float2half_rn(acc[mt][nt][2]);
                pB[DIMH] = __float2half_rn(acc[mt][nt][3]);
            } else {
                const int m2A = mA - 512, m2B = mB - 512;
                const int hA = m2A >> 6, dA = m2A & 63;
                const int hB = m2B >> 6, dB = m2B & 63;
                *(uint32_t*)(gv + ((long)(b * 8 + hA) * DIMH + dA) * S_ + col) =
                    f2h2(acc[mt][nt][0], acc[mt][nt][1]);
                *(uint32_t*)(gv + ((long)(b * 8 + hB) * DIMH + dB) * S_ + col) =
                    f2h2(acc[mt][nt][2], acc[mt][nt][3]);
            }
        }
    }
}

// ---------------------------------------------------------------------------
// Tensor-core flash attention, split-KV, double-buffered cp.async K/V staging.
// Compute body identical to the validated R7/R8/R10 kernel; only the staging
// mechanism changed (sync LDG/STS -> cp.async ring of 2).
// ---------------------------------------------------------------------------
#define KS_STRIDE 72     // halves per K/Q smem row
#define VS_STRIDE 136    // halves per V smem row
#define QS_HALVES (T_ * KS_STRIDE)          // 4608
#define KS_HALVES (128 * KS_STRIDE)         // 9216
#define VS_HALVES (DIMH * VS_STRIDE)        // 8704
#define ATTN_SMEM ((QS_HALVES + 2 * KS_HALVES + 2 * VS_HALVES) * 2)   // 80896 B

__global__ __launch_bounds__(128)
void attn_f16(const __half* __restrict__ q16, const __half* __restrict__ k16,
              const __half* __restrict__ v16, float* __restrict__ opart,
              float* __restrict__ ml)
{
    extern __shared__ __half smd[];
    __half* Qs  = smd;
    __half* Ksb = smd + QS_HALVES;                  // 2 x KS_HALVES
    __half* Vsb = smd + QS_HALVES + 2 * KS_HALVES;  // 2 x VS_HALVES

    const int sp  = blockIdx.x;
    const int bh  = blockIdx.y;
    const int tid = threadIdx.x;
    const int warp = tid >> 5;
    const int lane = tid & 31;
    const int g   = lane >> 2;
    const int tg  = lane & 3;
    const int wm  = warp * 16;

    const __half* kb = k16 + ((long)bh * S_ + sp * S_PER) * DIMH;
    const __half* vb = v16 + (long)bh * DIMH * S_ + sp * S_PER;
    const int NT = S_PER / 128;   // 8

    // async tile loader (same addresses as the validated sync loops)
    auto issue_tile = [&](int tile, int buf) {
        __half* Ks = Ksb + buf * KS_HALVES;
        __half* Vs = Vsb + buf * VS_HALVES;
        #pragma unroll
        for (int t = 0; t < 8; t++) {            // K: 128 x 64 halves
            const int idx = tid + t * 128;
            const int r = idx >> 3, c8 = idx & 7;
            const __half* src = &kb[(long)(tile * 128 + r) * DIMH + c8 * 8];
            asm volatile("cp.async.cg.shared.global [%0], [%1], 16;"
                         :: "r"(smem_u32(&Ks[r * KS_STRIDE + c8 * 8])), "l"(src));
        }
        #pragma unroll
        for (int t = 0; t < 8; t++) {            // V: 64 x 128 halves
            const int idx = tid + t * 128;
            const int r = idx >> 4, c16 = idx & 15;
            const __half* src = &vb[(long)r * S_ + tile * 128 + c16 * 8];
            asm volatile("cp.async.cg.shared.global [%0], [%1], 16;"
                         :: "r"(smem_u32(&Vs[r * VS_STRIDE + c16 * 8])), "l"(src));
        }
        asm volatile("cp.async.commit_group;" ::: "memory");
    };

    issue_tile(0, 0);
    issue_tile(1, 1);

    // stage Q (64 x 64 halves) while the first tiles are in flight
    const __half* qb = q16 + (long)bh * T_ * DIMH;
    #pragma unroll
    for (int t = 0; t < 4; t++) {
        const int idx = tid + t * 128;
        const int r = idx >> 3, c8 = idx & 7;
        *(uint4*)&Qs[r * KS_STRIDE + c8 * 8] = *(const uint4*)&qb[r * DIMH + c8 * 8];
    }
    __syncthreads();

    // Q fragments: 4 k-steps over d
    uint32_t aq[4][4];
    #pragma unroll
    for (int ks = 0; ks < 4; ks++) {
        aq[ks][0] = *(const uint32_t*)&Qs[(wm + g)     * KS_STRIDE + ks * 16 + 2 * tg];
        aq[ks][1] = *(const uint32_t*)&Qs[(wm + g + 8) * KS_STRIDE + ks * 16 + 2 * tg];
        aq[ks][2] = *(const uint32_t*)&Qs[(wm + g)     * KS_STRIDE + ks * 16 + 2 * tg + 8];
        aq[ks][3] = *(const uint32_t*)&Qs[(wm + g + 8) * KS_STRIDE + ks * 16 + 2 * tg + 8];
    }

    float accO[8][4];
    #pragma unroll
    for (int nt = 0; nt < 8; nt++)
        #pragma unroll
        for (int i = 0; i < 4; i++) accO[nt][i] = 0.f;
    float m0r = -1e30f, m1r = -1e30f, l0 = 0.f, l1 = 0.f;

    for (int tile = 0; tile < NT; tile++) {
        const int buf = tile & 1;
        __half* Ks = Ksb + buf * KS_HALVES;
        __half* Vs = Vsb + buf * VS_HALVES;

        if (tile + 1 < NT)
            asm volatile("cp.async.wait_group 1;" ::: "memory");
        else
            asm volatile("cp.async.wait_group 0;" ::: "memory");
        __syncthreads();

        // QK^T
        float accS[16][4];
        #pragma unroll
        for (int nt = 0; nt < 16; nt++)
            #pragma unroll
            for (int i = 0; i < 4; i++) accS[nt][i] = 0.f;

        #pragma unroll
        for (int ks = 0; ks < 4; ks++) {
            #pragma unroll
            for (int nt = 0; nt < 16; nt++) {
                uint32_t b0 = *(const uint32_t*)&Ks[(nt * 8 + g) * KS_STRIDE + ks * 16 + 2 * tg];
                uint32_t b1 = *(const uint32_t*)&Ks[(nt * 8 + g) * KS_STRIDE + ks * 16 + 2 * tg + 8];
                asm volatile(
                    "mma.sync.aligned.m16n8k16.row.col.f32.f16.f16.f32 "
                    "{%0,%1,%2,%3}, {%4,%5,%6,%7}, {%8,%9}, {%0,%1,%2,%3};"
                    : "+f"(accS[nt][0]), "+f"(accS[nt][1]),
                      "+f"(accS[nt][2]), "+f"(accS[nt][3])
                    : "r"(aq[ks][0]), "r"(aq[ks][1]), "r"(aq[ks][2]), "r"(aq[ks][3]),
                      "r"(b0), "r"(b1));
            }
        }

        // online softmax (rows g and g+8)
        float mx0 = -1e30f, mx1 = -1e30f;
        #pragma unroll
        for (int nt = 0; nt < 16; nt++) {
            mx0 = fmaxf(mx0, fmaxf(accS[nt][0], accS[nt][1]));
            mx1 = fmaxf(mx1, fmaxf(accS[nt][2], accS[nt][3]));
        }
        mx0 = fmaxf(mx0, __shfl_xor_sync(0xffffffffu, mx0, 1));
        mx0 = fmaxf(mx0, __shfl_xor_sync(0xffffffffu, mx0, 2));
        mx1 = fmaxf(mx1, __shfl_xor_sync(0xffffffffu, mx1, 1));
        mx1 = fmaxf(mx1, __shfl_xor_sync(0xffffffffu, mx1, 2));

        const float mn0 = fmaxf(m0r, mx0);
        const float mn1 = fmaxf(m1r, mx1);
        const float cr0 = __expf(m0r - mn0);
        const float cr1 = __expf(m1r - mn1);
        m0r = mn0; m1r = mn1;

        float s0 = 0.f, s1 = 0.f;
        #pragma unroll
        for (int nt = 0; nt < 16; nt++) {
            accS[nt][0] = __expf(accS[nt][0] - mn0);
            accS[nt][1] = __expf(accS[nt][1] - mn0);
            accS[nt][2] = __expf(accS[nt][2] - mn1);
            accS[nt][3] = __expf(accS[nt][3] - mn1);
            s0 += accS[nt][0] + accS[nt][1];
            s1 += accS[nt][2] + accS[nt][3];
        }
        s0 += __shfl_xor_sync(0xffffffffu, s0, 1);
        s0 += __shfl_xor_sync(0xffffffffu, s0, 2);
        s1 += __shfl_xor_sync(0xffffffffu, s1, 1);
        s1 += __shfl_xor_sync(0xffffffffu, s1, 2);
        l0 = l0 * cr0 + s0;
        l1 = l1 * cr1 + s1;

        #pragma unroll
        for (int nt = 0; nt < 8; nt++) {
            accO[nt][0] *= cr0; accO[nt][1] *= cr0;
            accO[nt][2] *= cr1; accO[nt][3] *= cr1;
        }

        // P -> half2 A-fragments
        uint32_t ap[8][4];
        #pragma unroll
        for (int ks = 0; ks < 8; ks++) {
            ap[ks][0] = f2h2(accS[2*ks][0],   accS[2*ks][1]);
            ap[ks][1] = f2h2(accS[2*ks][2],   accS[2*ks][3]);
            ap[ks][2] = f2h2(accS[2*ks+1][0], accS[2*ks+1][1]);
            ap[ks][3] = f2h2(accS[2*ks+1][2], accS[2*ks+1][3]);
        }

        // P @ V
        #pragma unroll
        for (int ks = 0; ks < 8; ks++) {
            #pragma unroll
            for (int nt = 0; nt < 8; nt++) {
                uint32_t b0 = *(const uint32_t*)&Vs[(nt * 8 + g) * VS_STRIDE + ks * 16 + 2 * tg];
                uint32_t b1 = *(const uint32_t*)&Vs[(nt * 8 + g) * VS_STRIDE + ks * 16 + 2 * tg + 8];
                asm volatile(
                    "mma.sync.aligned.m16n8k16.row.col.f32.f16.f16.f32 "
                    "{%0,%1,%2,%3}, {%4,%5,%6,%7}, {%8,%9}, {%0,%1,%2,%3};"
                    : "+f"(accO[nt][0]), "+f"(accO[nt][1]),
                      "+f"(accO[nt][2]), "+f"(accO[nt][3])
                    : "r"(ap[ks][0]), "r"(ap[ks][1]), "r"(ap[ks][2]), "r"(ap[ks][3]),
                      "r"(b0), "r"(b1));
            }
        }

        __syncthreads();   // all reads of buf done before it is refilled
        if (tile + 2 < NT)
            issue_tile(tile + 2, buf);
    }

    // write partials (unnormalized) + (m, l)
    float* op = opart + ((long)(sp * BH_ + bh) * T_) * DIMH;
    const int rA = wm + g, rB = wm + g + 8;
    #pragma unroll
    for (int nt = 0; nt < 8; nt++) {
        const int col = nt * 8 + 2 * tg;
        *(float2*)&op[rA * DIMH + col] = make_float2(accO[nt][0], accO[nt][1]);
        *(float2*)&op[rB * DIMH + col] = make_float2(accO[nt][2], accO[nt][3]);
    }
    if (tg == 0) {
        float* mlp = ml + ((long)(sp * BH_ + bh) * T_) * 2;
        mlp[rA * 2] = m0r; mlp[rA * 2 + 1] = l0;
        mlp[rB * 2] = m1r; mlp[rB * 2 + 1] = l1;
    }
}

// ---------------------------------------------------------------------------
// split-KV combine -> g_ao (B,T,inner) f32   [validated]
// ---------------------------------------------------------------------------
__global__ void attn_combine(const float* __restrict__ opart,
                             const float* __restrict__ ml, float* __restrict__ ao)
{
    const int bh  = blockIdx.x;
    const int b   = bh >> 3;
    const int h   = bh & 7;
    const int tid = threadIdx.x;       // 128
    const int t   = tid >> 1;
    const int d0  = (tid & 1) * 32;

    float m[SPLIT], l[SPLIT];
    float M = -1e30f;
    #pragma unroll
    for (int i = 0; i < SPLIT; i++) {
        m[i] = ml[((long)(i * BH_ + bh) * T_ + t) * 2];
        l[i] = ml[((long)(i * BH_ + bh) * T_ + t) * 2 + 1];
        M = fmaxf(M, m[i]);
    }
    float w[SPLIT], L = 0.f;
    #pragma unroll
    for (int i = 0; i < SPLIT; i++) {
        w[i] = __expf(m[i] - M);
        L += w[i] * l[i];
    }
    const float inv = 1.f / L;

    float* dst = ao + ((long)(b * T_ + t)) * INNER + h * DIMH + d0;
    #pragma unroll
    for (int d = 0; d < 32; d++) {
        float o = 0.f;
        #pragma unroll
        for (int i = 0; i < SPLIT; i++)
            o += w[i] * opart[((long)(i * BH_ + bh) * T_ + t) * DIMH + d0 + d];
        dst[d] = o * inv;
    }
}

// ---------------------------------------------------------------------------
extern "C" void kernel_launch(void* const* d_in, const int* in_sizes, int n_in,
                              void* d_out, int out_size)
{
    const float* vis  = (const float*)d_in[0];
    const float* lang = (const float*)d_in[1];
    // d_in[2] = mask (unused)
    const float* Wq   = (const float*)d_in[3];
    const float* Wk   = (const float*)d_in[4];
    const float* Wv   = (const float*)d_in[5];
    const float* Wo   = (const float*)d_in[6];
    float* out = (float*)d_out;

    float *q, *ao, *op, *ml;
    __half *w16, *lang16, *ao16, *q16, *k16, *v16;
    uint32_t *v16p, *wqT, *woT;
    cudaGetSymbolAddress((void**)&q,      g_q);
    cudaGetSymbolAddress((void**)&ao,     g_ao);
    cudaGetSymbolAddress((void**)&w16,    g_w16);
    cudaGetSymbolAddress((void**)&lang16, g_lang16);
    cudaGetSymbolAddress((void**)&ao16,   g_ao16);
    cudaGetSymbolAddress((void**)&wqT,    g_wqT);
    cudaGetSymbolAddress((void**)&woT,    g_woT);
    cudaGetSymbolAddress((void**)&v16p,   g_v16p);
    cudaGetSymbolAddress((void**)&q16,    g_q16);
    cudaGetSymbolAddress((void**)&k16,    g_k16);
    cudaGetSymbolAddress((void**)&v16,    g_v16);
    cudaGetSymbolAddress((void**)&op,     g_op);
    cudaGetSymbolAddress((void**)&ml,     g_ml);

    cudaFuncSetAttribute(gemm_kv_f16, cudaFuncAttributeMaxDynamicSharedMemorySize,
                         KV_SMEM);
    cudaFuncSetAttribute(gemm_proj, cudaFuncAttributeMaxDynamicSharedMemorySize,
                         KV_SMEM);
    cudaFuncSetAttribute(attn_f16, cudaFuncAttributeMaxDynamicSharedMemorySize,
                         ATTN_SMEM);

    // fused prep + vis pack
    prep_all<<<4096, 256>>>(Wk, Wv, Wq, Wo, lang, w16, wqT, woT, lang16);
    prep_vis16<<<(int)(((long)B_ * (C_ / 2) * S_) / 256), 256>>>(vis, v16p);

    // q projection (fp16 mma) -> f32 q, then validated repack to q16
    gemm_proj<<<dim3(INNER / 128, (B_ * T_) / 128), 256, KV_SMEM>>>(lang16, wqT, q);
    prep_q16<<<B_ * T_ * INNER / 256, 256>>>(q, q16);

    // fused k+v projection (fp16 tensor cores, cp.async pipeline)
    gemm_kv_f16<<<dim3(S_ / 128, (2 * INNER) / 128, B_), 256, KV_SMEM>>>(w16, v16p, k16, v16);

    // flash attention (tensor cores, split-KV, cp.async) + combine + fp16 repack
    attn_f16<<<dim3(SPLIT, BH_), 128, ATTN_SMEM>>>(q16, k16, v16, op, ml);
    attn_combine<<<BH_, 128>>>(op, ml, ao);
    conv16<<<B_ * T_ * INNER / 256, 256>>>(ao, ao16);

    // output projection (fp16 mma) -> f32 out
    gemm_proj<<<dim3(C_ / 128, (B_ * T_) / 128), 256, KV_SMEM>>>(ao16, woT, out);
}

// round 13
// speedup vs baseline: 1.0018x; 1.0018x over previous
#include <cuda_runtime.h>
#include <cuda_fp16.h>
#include <cstdint>

// Problem constants
#define B_    16
#define T_    64
#define C_    512
#define S_    4096
#define INNER 512
#define DIMH  64
#define NHEAD 8
#define BH_   (B_ * NHEAD)
#define SPLIT 4
#define S_PER (S_ / SPLIT)      // 1024

// Scratch (device globals; no allocations allowed)
__device__ float    g_q    [B_ * T_ * INNER];             // q projection f32
__device__ float    g_ao   [B_ * T_ * INNER];             // attention out f32
__device__ __half   g_w16  [2 * INNER * C_];              // concat(Wk,Wv) fp16
__device__ __half   g_lang16[B_ * T_ * C_];               // lang fp16 [1024][512]
__device__ __half   g_ao16 [B_ * T_ * INNER];             // attention out fp16
__device__ uint32_t g_wqT  [(C_ / 2) * INNER];            // Wq^T pair-packed [256][512]
__device__ uint32_t g_woT  [(INNER / 2) * C_];            // Wo^T pair-packed [256][512]
__device__ uint32_t g_v16p [(long)B_ * (C_ / 2) * S_];    // vis fp16 pair-packed
__device__ __half   g_q16  [BH_ * T_ * DIMH];             // q fp16 (bh,t,d), pre-scaled
__device__ __half   g_k16  [(long)BH_ * S_ * DIMH];       // K fp16 s-major (bh,s,d)
__device__ __half   g_v16  [(long)BH_ * DIMH * S_];       // V fp16 d-major (bh,d,s)
__device__ float    g_op   [(long)SPLIT * BH_ * T_ * DIMH]; // partial O
__device__ float    g_ml   [SPLIT * BH_ * T_ * 2];        // partial (m,l)

// pack two fp32 -> one .f16x2 register (lo = first arg)
__device__ __forceinline__ uint32_t f2h2(float lo, float hi) {
    uint32_t r;
    asm("cvt.rn.f16x2.f32 %0, %1, %2;" : "=r"(r) : "f"(hi), "f"(lo));
    return r;
}

__device__ __forceinline__ uint32_t smem_u32(const void* p) {
    uint32_t a;
    asm("{ .reg .u64 t; cvta.to.shared.u64 t, %1; cvt.u32.u64 %0, t; }" : "=r"(a) : "l"(p));
    return a;
}

// ---------------------------------------------------------------------------
__global__ void conv16(const float* __restrict__ src, __half* __restrict__ dst)
{
    const int i = blockIdx.x * 256 + threadIdx.x;
    dst[i] = __float2half_rn(src[i]);
}

// fused prep: w16 concat (blocks 0..1023), Wq^T pack (1024..1535),
// Wo^T pack (1536..2047), lang conv (2048..4095)
__global__ void prep_all(const float* __restrict__ Wk, const float* __restrict__ Wv,
                         const float* __restrict__ Wq, const float* __restrict__ Wo,
                         const float* __restrict__ lang,
                         __half* __restrict__ w16, uint32_t* __restrict__ wqT,
                         uint32_t* __restrict__ woT, __half* __restrict__ lang16)
{
    const int blk = blockIdx.x;
    if (blk < 1024) {
        const int i = blk * 256 + threadIdx.x;
        w16[i]              = __float2half_rn(Wk[i]);
        w16[INNER * C_ + i] = __float2half_rn(Wv[i]);
    } else if (blk < 1536) {
        const int idx = (blk - 1024) * 256 + threadIdx.x;   // k2*512 + n
        const int n  = idx & 511;
        const int k2 = idx >> 9;
        const float* s = Wq + n * 512 + 2 * k2;
        wqT[idx] = f2h2(s[0], s[1]);
    } else if (blk < 2048) {
        const int idx = (blk - 1536) * 256 + threadIdx.x;
        const int n  = idx & 511;
        const int k2 = idx >> 9;
        const float* s = Wo + n * 512 + 2 * k2;
        woT[idx] = f2h2(s[0], s[1]);
    } else {
        const int i = (blk - 2048) * 256 + threadIdx.x;
        lang16[i] = __float2half_rn(lang[i]);
    }
}

__global__ void prep_vis16(const float* __restrict__ vis, uint32_t* __restrict__ vp)
{
    const long i  = (long)blockIdx.x * 256 + threadIdx.x;
    const long s  = i & (S_ - 1);
    const long c2 = (i >> 12) & 255;
    const long b  = i >> 20;
    const float* src = vis + (((b * C_) + 2 * c2) << 12) + s;
    vp[i] = f2h2(src[0], src[S_]);
}

// q f32 (B,T,inner) -> q16 (bh,t,d), scaled by 0.125   [validated]
__global__ void prep_q16(const float* __restrict__ q, __half* __restrict__ q16)
{
    const int i = blockIdx.x * 256 + threadIdx.x;   // 0 .. 524287
    const int d = i & 63;
    const int h = (i >> 6) & 7;
    const int t = (i >> 9) & 63;
    const int b = i >> 15;
    q16[(((b * 8 + h) * T_) + t) * DIMH + d] = __float2half_rn(q[i] * 0.125f);
}

// ---------------------------------------------------------------------------
// shared tile sizes (kv kernel + its clone)
#define NSTAGE   4
#define A_ST_U32 (128 * 20)
#define B_ST_U32 (16 * 136)
#define KV_SMEM  (NSTAGE * (A_ST_U32 + B_ST_U32) * 4)   // 75776 bytes

// ---------------------------------------------------------------------------
// Projection GEMM: Cf[1024][512] = A16[1024][512] @ (packed B)[512][512]
// Verbatim clone of gemm_kv_f16 mainloop with N=512 and f32 epilogue.  [validated]
// ---------------------------------------------------------------------------
__global__ __launch_bounds__(256)
void gemm_proj(const __half* __restrict__ A16,      // [1024][512]
               const uint32_t* __restrict__ Bp,     // [256][512] pairs k2-major
               float* __restrict__ Cf)              // [1024][512]
{
    extern __shared__ uint32_t smdyn[];
    uint32_t (*As)[128][20]  = (uint32_t(*)[128][20])smdyn;
    uint32_t (*Bs)[16][136]  = (uint32_t(*)[16][136])(smdyn + NSTAGE * A_ST_U32);

    const int m0 = blockIdx.y * 128;
    const int n0 = blockIdx.x * 128;
    const uint32_t* Ap = (const uint32_t*)A16;               // pair view [1024][256]

    const int tid  = threadIdx.x;
    const int warp = tid >> 5;
    const int lane = tid & 31;
    const int wm   = (warp >> 1) * 32;
    const int wn   = (warp & 1) * 64;
    const int g    = lane >> 2;
    const int tg   = lane & 3;

    float acc[2][8][4];
    #pragma unroll
    for (int mt = 0; mt < 2; mt++)
        #pragma unroll
        for (int nt = 0; nt < 8; nt++)
            #pragma unroll
            for (int i = 0; i < 4; i++)
                acc[mt][nt][i] = 0.f;

    auto issue = [&](int ch, int st) {
        const int kc2 = ch * 16;
        #pragma unroll
        for (int t = 0; t < 2; t++) {
            const int idx = tid + t * 256;
            const int r = idx >> 2, p4 = (idx & 3) * 4;
            const uint32_t* src = &Ap[(long)(m0 + r) * (C_ / 2) + kc2 + p4];
            asm volatile("cp.async.cg.shared.global [%0], [%1], 16;"
                         :: "r"(smem_u32(&As[st][r][p4])), "l"(src));
        }
        #pragma unroll
        for (int t = 0; t < 2; t++) {
            const int idx = tid + t * 256;
            const int r = idx >> 5, c4 = (idx & 31) * 4;
            const uint32_t* src = &Bp[(long)(kc2 + r) * 512 + n0 + c4];
            asm volatile("cp.async.cg.shared.global [%0], [%1], 16;"
                         :: "r"(smem_u32(&Bs[st][r][c4])), "l"(src));
        }
        asm volatile("cp.async.commit_group;" ::: "memory");
    };

    issue(0, 0); issue(1, 1); issue(2, 2);

    const int NCH = C_ / 32;   // 16
    for (int ch = 0; ch < NCH; ++ch) {
        const int st = ch & (NSTAGE - 1);
        asm volatile("cp.async.wait_group 2;" ::: "memory");
        __syncthreads();

        #pragma unroll
        for (int ks = 0; ks < 2; ks++) {
            const int kb = ks * 8;
            uint32_t bf[8][2];
            #pragma unroll
            for (int nt = 0; nt < 8; nt++) {
                bf[nt][0] = Bs[st][kb + tg]    [wn + nt * 8 + g];
                bf[nt][1] = Bs[st][kb + tg + 4][wn + nt * 8 + g];
            }
            #pragma unroll
            for (int mt = 0; mt < 2; mt++) {
                const int mi = wm + mt * 16 + g;
                uint32_t a0 = As[st][mi]    [kb + tg];
                uint32_t a1 = As[st][mi + 8][kb + tg];
                uint32_t a2 = As[st][mi]    [kb + tg + 4];
                uint32_t a3 = As[st][mi + 8][kb + tg + 4];
                #pragma unroll
                for (int nt = 0; nt < 8; nt++) {
                    asm volatile(
                        "mma.sync.aligned.m16n8k16.row.col.f32.f16.f16.f32 "
                        "{%0,%1,%2,%3}, {%4,%5,%6,%7}, {%8,%9}, {%0,%1,%2,%3};"
                        : "+f"(acc[mt][nt][0]), "+f"(acc[mt][nt][1]),
                          "+f"(acc[mt][nt][2]), "+f"(acc[mt][nt][3])
                        : "r"(a0), "r"(a1), "r"(a2), "r"(a3),
                          "r"(bf[nt][0]), "r"(bf[nt][1]));
                }
            }
        }

        if (ch + NSTAGE - 1 < NCH)
            issue(ch + NSTAGE - 1, (ch + NSTAGE - 1) & (NSTAGE - 1));
    }

    #pragma unroll
    for (int mt = 0; mt < 2; mt++) {
        const int rA = m0 + wm + mt * 16 + g;
        const int rB = rA + 8;
        #pragma unroll
        for (int nt = 0; nt < 8; nt++) {
            const int col = n0 + wn + nt * 8 + 2 * tg;
            *(float2*)&Cf[(long)rA * 512 + col] = make_float2(acc[mt][nt][0], acc[mt][nt][1]);
            *(float2*)&Cf[(long)rB * 512 + col] = make_float2(acc[mt][nt][2], acc[mt][nt][3]);
        }
    }
}

// ---------------------------------------------------------------------------
// Fused k/v projection, fp16 mma, 4-stage cp.async. Mainloop identical to the
// validated R8/R10/R12 kernel. NEW: K epilogue stages accumulators through a
// smem tile (128 m x 130-stride s, halves) and emits fully coalesced 128B row
// writes (was: 2-byte scattered stores with ~16x sector inflation).
// ---------------------------------------------------------------------------
#define KT_STRIDE 130

__global__ __launch_bounds__(256)
void gemm_kv_f16(const __half* __restrict__ A16,      // [1024][512]
                 const uint32_t* __restrict__ Bp,     // [16][256][4096] pairs
                 __half* __restrict__ gk,             // (bh,s,d)
                 __half* __restrict__ gv)             // (bh,d,s)
{
    extern __shared__ uint32_t smdyn[];
    uint32_t (*As)[128][20]  = (uint32_t(*)[128][20])smdyn;
    uint32_t (*Bs)[16][136]  = (uint32_t(*)[16][136])(smdyn + NSTAGE * A_ST_U32);

    const int b  = blockIdx.z;
    const int m0 = blockIdx.y * 128;
    const int n0 = blockIdx.x * 128;
    const uint32_t* Ap = (const uint32_t*)A16;
    const uint32_t* Bb = Bp + (long)b * (C_ / 2) * S_;

    const int tid  = threadIdx.x;
    const int warp = tid >> 5;
    const int lane = tid & 31;
    const int wm   = (warp >> 1) * 32;
    const int wn   = (warp & 1) * 64;
    const int g    = lane >> 2;
    const int tg   = lane & 3;

    float acc[2][8][4];
    #pragma unroll
    for (int mt = 0; mt < 2; mt++)
        #pragma unroll
        for (int nt = 0; nt < 8; nt++)
            #pragma unroll
            for (int i = 0; i < 4; i++)
                acc[mt][nt][i] = 0.f;

    auto issue = [&](int ch, int st) {
        const int kc2 = ch * 16;
        #pragma unroll
        for (int t = 0; t < 2; t++) {
            const int idx = tid + t * 256;
            const int r = idx >> 2, p4 = (idx & 3) * 4;
            const uint32_t* src = &Ap[(long)(m0 + r) * (C_ / 2) + kc2 + p4];
            asm volatile("cp.async.cg.shared.global [%0], [%1], 16;"
                         :: "r"(smem_u32(&As[st][r][p4])), "l"(src));
        }
        #pragma unroll
        for (int t = 0; t < 2; t++) {
            const int idx = tid + t * 256;
            const int r = idx >> 5, c4 = (idx & 31) * 4;
            const uint32_t* src = &Bb[(long)(kc2 + r) * S_ + n0 + c4];
            asm volatile("cp.async.cg.shared.global [%0], [%1], 16;"
                         :: "r"(smem_u32(&Bs[st][r][c4])), "l"(src));
        }
        asm volatile("cp.async.commit_group;" ::: "memory");
    };

    issue(0, 0); issue(1, 1); issue(2, 2);

    const int NCH = C_ / 32;   // 16
    for (int ch = 0; ch < NCH; ++ch) {
        const int st = ch & (NSTAGE - 1);
        asm volatile("cp.async.wait_group 2;" ::: "memory");
        __syncthreads();

        #pragma unroll
        for (int ks = 0; ks < 2; ks++) {
            const int kb = ks * 8;
            uint32_t bf[8][2];
            #pragma unroll
            for (int nt = 0; nt < 8; nt++) {
                bf[nt][0] = Bs[st][kb + tg]    [wn + nt * 8 + g];
                bf[nt][1] = Bs[st][kb + tg + 4][wn + nt * 8 + g];
            }
            #pragma unroll
            for (int mt = 0; mt < 2; mt++) {
                const int mi = wm + mt * 16 + g;
                uint32_t a0 = As[st][mi]    [kb + tg];
                uint32_t a1 = As[st][mi + 8][kb + tg];
                uint32_t a2 = As[st][mi]    [kb + tg + 4];
                uint32_t a3 = As[st][mi + 8][kb + tg + 4];
                #pragma unroll
                for (int nt = 0; nt < 8; nt++) {
                    asm volatile(
                        "mma.sync.aligned.m16n8k16.row.col.f32.f16.f16.f32 "
                        "{%0,%1,%2,%3}, {%4,%5,%6,%7}, {%8,%9}, {%0,%1,%2,%3};"
                        : "+f"(acc[mt][nt][0]), "+f"(acc[mt][nt][1]),
                          "+f"(acc[mt][nt][2]), "+f"(acc[mt][nt][3])
                        : "r"(a0), "r"(a1), "r"(a2), "r"(a3),
                          "r"(bf[nt][0]), "r"(bf[nt][1]));
                }
            }
        }

        if (ch + NSTAGE - 1 < NCH)
            issue(ch + NSTAGE - 1, (ch + NSTAGE - 1) & (NSTAGE - 1));
    }

    if (m0 < 512) {
        // K epilogue: accumulators -> smem tile [m][s] -> coalesced (bh,s,d) rows
        __half* tile = (__half*)smdyn;   // 128 x KT_STRIDE halves (33 KB)
        __syncthreads();                 // all mma fragment reads of smem done
        #pragma unroll
        for (int mt = 0; mt < 2; mt++) {
            const int lmA = wm + mt * 16 + g;
            const int lmB = lmA + 8;
            #pragma unroll
            for (int nt = 0; nt < 8; nt++) {
                const int lc = wn + nt * 8 + 2 * tg;
                tile[lmA * KT_STRIDE + lc]     = __float2half_rn(acc[mt][nt][0]);
                tile[lmA * KT_STRIDE + lc + 1] = __float2half_rn(acc[mt][nt][1]);
                tile[lmB * KT_STRIDE + lc]     = __float2half_rn(acc[mt][nt][2]);
                tile[lmB * KT_STRIDE + lc + 1] = __float2half_rn(acc[mt][nt][3]);
            }
        }
        __syncthreads();
        // 256 rows = 2 heads x 128 s; one warp-row = 32 lanes x 4B = 128B store
        #pragma unroll
        for (int it = 0; it < 32; it++) {
            const int row = warp * 32 + it;
            const int hh  = row >> 7;          // 0 or 1
            const int sl  = row & 127;         // local s
            const int h   = (m0 >> 6) + hh;
            const __half lo = tile[(hh * 64 + 2 * lane)     * KT_STRIDE + sl];
            const __half hi = tile[(hh * 64 + 2 * lane + 1) * KT_STRIDE + sl];
            __half2 v; v.x = lo; v.y = hi;
            *(__half2*)(gk + ((long)(b * 8 + h) * S_ + n0 + sl) * DIMH + 2 * lane) = v;
        }
    } else {
        // V epilogue (unchanged, half2 contiguous-ish)
        #pragma unroll
        for (int mt = 0; mt < 2; mt++) {
            const int mA = m0 + wm + mt * 16 + g;
            const int mB = mA + 8;
            #pragma unroll
            for (int nt = 0; nt < 8; nt++) {
                const int col = n0 + wn + nt * 8 + 2 * tg;
                const int m2A = mA - 512, m2B = mB - 512;
                const int hA = m2A >> 6, dA = m2A & 63;
                const int hB = m2B >> 6, dB = m2B & 63;
                *(uint32_t*)(gv + ((long)(b * 8 + hA) * DIMH + dA) * S_ + col) =
                    f2h2(acc[mt][nt][0], acc[mt][nt][1]);
                *(uint32_t*)(gv + ((long)(b * 8 + hB) * DIMH + dB) * S_ + col) =
                    f2h2(acc[mt][nt][2], acc[mt][nt][3]);
            }
        }
    }
}

// ---------------------------------------------------------------------------
// Tensor-core flash attention, split-KV, double-buffered cp.async staging.
// [validated R12]
// ---------------------------------------------------------------------------
#define KS_STRIDE 72     // halves per K/Q smem row
#define VS_STRIDE 136    // halves per V smem row
#define QS_HALVES (T_ * KS_STRIDE)          // 4608
#define KS_HALVES (128 * KS_STRIDE)         // 9216
#define VS_HALVES (DIMH * VS_STRIDE)        // 8704
#define ATTN_SMEM ((QS_HALVES + 2 * KS_HALVES + 2 * VS_HALVES) * 2)   // 80896 B

__global__ __launch_bounds__(128)
void attn_f16(const __half* __restrict__ q16, const __half* __restrict__ k16,
              const __half* __restrict__ v16, float* __restrict__ opart,
              float* __restrict__ ml)
{
    extern __shared__ __half smd[];
    __half* Qs  = smd;
    __half* Ksb = smd + QS_HALVES;
    __half* Vsb = smd + QS_HALVES + 2 * KS_HALVES;

    const int sp  = blockIdx.x;
    const int bh  = blockIdx.y;
    const int tid = threadIdx.x;
    const int warp = tid >> 5;
    const int lane = tid & 31;
    const int g   = lane >> 2;
    const int tg  = lane & 3;
    const int wm  = warp * 16;

    const __half* kb = k16 + ((long)bh * S_ + sp * S_PER) * DIMH;
    const __half* vb = v16 + (long)bh * DIMH * S_ + sp * S_PER;
    const int NT = S_PER / 128;   // 8

    auto issue_tile = [&](int tile, int buf) {
        __half* Ks = Ksb + buf * KS_HALVES;
        __half* Vs = Vsb + buf * VS_HALVES;
        #pragma unroll
        for (int t = 0; t < 8; t++) {
            const int idx = tid + t * 128;
            const int r = idx >> 3, c8 = idx & 7;
            const __half* src = &kb[(long)(tile * 128 + r) * DIMH + c8 * 8];
            asm volatile("cp.async.cg.shared.global [%0], [%1], 16;"
                         :: "r"(smem_u32(&Ks[r * KS_STRIDE + c8 * 8])), "l"(src));
        }
        #pragma unroll
        for (int t = 0; t < 8; t++) {
            const int idx = tid + t * 128;
            const int r = idx >> 4, c16 = idx & 15;
            const __half* src = &vb[(long)r * S_ + tile * 128 + c16 * 8];
            asm volatile("cp.async.cg.shared.global [%0], [%1], 16;"
                         :: "r"(smem_u32(&Vs[r * VS_STRIDE + c16 * 8])), "l"(src));
        }
        asm volatile("cp.async.commit_group;" ::: "memory");
    };

    issue_tile(0, 0);
    issue_tile(1, 1);

    const __half* qb = q16 + (long)bh * T_ * DIMH;
    #pragma unroll
    for (int t = 0; t < 4; t++) {
        const int idx = tid + t * 128;
        const int r = idx >> 3, c8 = idx & 7;
        *(uint4*)&Qs[r * KS_STRIDE + c8 * 8] = *(const uint4*)&qb[r * DIMH + c8 * 8];
    }
    __syncthreads();

    uint32_t aq[4][4];
    #pragma unroll
    for (int ks = 0; ks < 4; ks++) {
        aq[ks][0] = *(const uint32_t*)&Qs[(wm + g)     * KS_STRIDE + ks * 16 + 2 * tg];
        aq[ks][1] = *(const uint32_t*)&Qs[(wm + g + 8) * KS_STRIDE + ks * 16 + 2 * tg];
        aq[ks][2] = *(const uint32_t*)&Qs[(wm + g)     * KS_STRIDE + ks * 16 + 2 * tg + 8];
        aq[ks][3] = *(const uint32_t*)&Qs[(wm + g + 8) * KS_STRIDE + ks * 16 + 2 * tg + 8];
    }

    float accO[8][4];
    #pragma unroll
    for (int nt = 0; nt < 8; nt++)
        #pragma unroll
        for (int i = 0; i < 4; i++) accO[nt][i] = 0.f;
    float m0r = -1e30f, m1r = -1e30f, l0 = 0.f, l1 = 0.f;

    for (int tile = 0; tile < NT; tile++) {
        const int buf = tile & 1;
        __half* Ks = Ksb + buf * KS_HALVES;
        __half* Vs = Vsb + buf * VS_HALVES;

        if (tile + 1 < NT)
            asm volatile("cp.async.wait_group 1;" ::: "memory");
        else
            asm volatile("cp.async.wait_group 0;" ::: "memory");
        __syncthreads();

        float accS[16][4];
        #pragma unroll
        for (int nt = 0; nt < 16; nt++)
            #pragma unroll
            for (int i = 0; i < 4; i++) accS[nt][i] = 0.f;

        #pragma unroll
        for (int ks = 0; ks < 4; ks++) {
            #pragma unroll
            for (int nt = 0; nt < 16; nt++) {
                uint32_t b0 = *(const uint32_t*)&Ks[(nt * 8 + g) * KS_STRIDE + ks * 16 + 2 * tg];
                uint32_t b1 = *(const uint32_t*)&Ks[(nt * 8 + g) * KS_STRIDE + ks * 16 + 2 * tg + 8];
                asm volatile(
                    "mma.sync.aligned.m16n8k16.row.col.f32.f16.f16.f32 "
                    "{%0,%1,%2,%3}, {%4,%5,%6,%7}, {%8,%9}, {%0,%1,%2,%3};"
                    : "+f"(accS[nt][0]), "+f"(accS[nt][1]),
                      "+f"(accS[nt][2]), "+f"(accS[nt][3])
                    : "r"(aq[ks][0]), "r"(aq[ks][1]), "r"(aq[ks][2]), "r"(aq[ks][3]),
                      "r"(b0), "r"(b1));
            }
        }

        float mx0 = -1e30f, mx1 = -1e30f;
        #pragma unroll
        for (int nt = 0; nt < 16; nt++) {
            mx0 = fmaxf(mx0, fmaxf(accS[nt][0], accS[nt][1]));
            mx1 = fmaxf(mx1, fmaxf(accS[nt][2], accS[nt][3]));
        }
        mx0 = fmaxf(mx0, __shfl_xor_sync(0xffffffffu, mx0, 1));
        mx0 = fmaxf(mx0, __shfl_xor_sync(0xffffffffu, mx0, 2));
        mx1 = fmaxf(mx1, __shfl_xor_sync(0xffffffffu, mx1, 1));
        mx1 = fmaxf(mx1, __shfl_xor_sync(0xffffffffu, mx1, 2));

        const float mn0 = fmaxf(m0r, mx0);
        const float mn1 = fmaxf(m1r, mx1);
        const float cr0 = __expf(m0r - mn0);
        const float cr1 = __expf(m1r - mn1);
        m0r = mn0; m1r = mn1;

        float s0 = 0.f, s1 = 0.f;
        #pragma unroll
        for (int nt = 0; nt < 16; nt++) {
            accS[nt][0] = __expf(accS[nt][0] - mn0);
            accS[nt][1] = __expf(accS[nt][1] - mn0);
            accS[nt][2] = __expf(accS[nt][2] - mn1);
            accS[nt][3] = __expf(accS[nt][3] - mn1);
            s0 += accS[nt][0] + accS[nt][1];
            s1 += accS[nt][2] + accS[nt][3];
        }
        s0 += __shfl_xor_sync(0xffffffffu, s0, 1);
        s0 += __shfl_xor_sync(0xffffffffu, s0, 2);
        s1 += __shfl_xor_sync(0xffffffffu, s1, 1);
        s1 += __shfl_xor_sync(0xffffffffu, s1, 2);
        l0 = l0 * cr0 + s0;
        l1 = l1 * cr1 + s1;

        #pragma unroll
        for (int nt = 0; nt < 8; nt++) {
            accO[nt][0] *= cr0; accO[nt][1] *= cr0;
            accO[nt][2] *= cr1; accO[nt][3] *= cr1;
        }

        uint32_t ap[8][4];
        #pragma unroll
        for (int ks = 0; ks < 8; ks++) {
            ap[ks][0] = f2h2(accS[2*ks][0],   accS[2*ks][1]);
            ap[ks][1] = f2h2(accS[2*ks][2],   accS[2*ks][3]);
            ap[ks][2] = f2h2(accS[2*ks+1][0], accS[2*ks+1][1]);
            ap[ks][3] = f2h2(accS[2*ks+1][2], accS[2*ks+1][3]);
        }

        #pragma unroll
        for (int ks = 0; ks < 8; ks++) {
            #pragma unroll
            for (int nt = 0; nt < 8; nt++) {
                uint32_t b0 = *(const uint32_t*)&Vs[(nt * 8 + g) * VS_STRIDE + ks * 16 + 2 * tg];
                uint32_t b1 = *(const uint32_t*)&Vs[(nt * 8 + g) * VS_STRIDE + ks * 16 + 2 * tg + 8];
                asm volatile(
                    "mma.sync.aligned.m16n8k16.row.col.f32.f16.f16.f32 "
                    "{%0,%1,%2,%3}, {%4,%5,%6,%7}, {%8,%9}, {%0,%1,%2,%3};"
                    : "+f"(accO[nt][0]), "+f"(accO[nt][1]),
                      "+f"(accO[nt][2]), "+f"(accO[nt][3])
                    : "r"(ap[ks][0]), "r"(ap[ks][1]), "r"(ap[ks][2]), "r"(ap[ks][3]),
                      "r"(b0), "r"(b1));
            }
        }

        __syncthreads();
        if (tile + 2 < NT)
            issue_tile(tile + 2, buf);
    }

    float* op = opart + ((long)(sp * BH_ + bh) * T_) * DIMH;
    const int rA = wm + g, rB = wm + g + 8;
    #pragma unroll
    for (int nt = 0; nt < 8; nt++) {
        const int col = nt * 8 + 2 * tg;
        *(float2*)&op[rA * DIMH + col] = make_float2(accO[nt][0], accO[nt][1]);
        *(float2*)&op[rB * DIMH + col] = make_float2(accO[nt][2], accO[nt][3]);
    }
    if (tg == 0) {
        float* mlp = ml + ((long)(sp * BH_ + bh) * T_) * 2;
        mlp[rA * 2] = m0r; mlp[rA * 2 + 1] = l0;
        mlp[rB * 2] = m1r; mlp[rB * 2 + 1] = l1;
    }
}

// ---------------------------------------------------------------------------
// split-KV combine -> g_ao (B,T,inner) f32   [validated]
// ---------------------------------------------------------------------------
__global__ void attn_combine(const float* __restrict__ opart,
                             const float* __restrict__ ml, float* __restrict__ ao)
{
    const int bh  = blockIdx.x;
    const int b   = bh >> 3;
    const int h   = bh & 7;
    const int tid = threadIdx.x;       // 128
    const int t   = tid >> 1;
    const int d0  = (tid & 1) * 32;

    float m[SPLIT], l[SPLIT];
    float M = -1e30f;
    #pragma unroll
    for (int i = 0; i < SPLIT; i++) {
        m[i] = ml[((long)(i * BH_ + bh) * T_ + t) * 2];
        l[i] = ml[((long)(i * BH_ + bh) * T_ + t) * 2 + 1];
        M = fmaxf(M, m[i]);
    }
    float w[SPLIT], L = 0.f;
    #pragma unroll
    for (int i = 0; i < SPLIT; i++) {
        w[i] = __expf(m[i] - M);
        L += w[i] * l[i];
    }
    const float inv = 1.f / L;

    float* dst = ao + ((long)(b * T_ + t)) * INNER + h * DIMH + d0;
    #pragma unroll
    for (int d = 0; d < 32; d++) {
        float o = 0.f;
        #pragma unroll
        for (int i = 0; i < SPLIT; i++)
            o += w[i] * opart[((long)(i * BH_ + bh) * T_ + t) * DIMH + d0 + d];
        dst[d] = o * inv;
    }
}

// ---------------------------------------------------------------------------
extern "C" void kernel_launch(void* const* d_in, const int* in_sizes, int n_in,
                              void* d_out, int out_size)
{
    const float* vis  = (const float*)d_in[0];
    const float* lang = (const float*)d_in[1];
    // d_in[2] = mask (unused)
    const float* Wq   = (const float*)d_in[3];
    const float* Wk   = (const float*)d_in[4];
    const float* Wv   = (const float*)d_in[5];
    const float* Wo   = (const float*)d_in[6];
    float* out = (float*)d_out;

    float *q, *ao, *op, *ml;
    __half *w16, *lang16, *ao16, *q16, *k16, *v16;
    uint32_t *v16p, *wqT, *woT;
    cudaGetSymbolAddress((void**)&q,      g_q);
    cudaGetSymbolAddress((void**)&ao,     g_ao);
    cudaGetSymbolAddress((void**)&w16,    g_w16);
    cudaGetSymbolAddress((void**)&lang16, g_lang16);
    cudaGetSymbolAddress((void**)&ao16,   g_ao16);
    cudaGetSymbolAddress((void**)&wqT,    g_wqT);
    cudaGetSymbolAddress((void**)&woT,    g_woT);
    cudaGetSymbolAddress((void**)&v16p,   g_v16p);
    cudaGetSymbolAddress((void**)&q16,    g_q16);
    cudaGetSymbolAddress((void**)&k16,    g_k16);
    cudaGetSymbolAddress((void**)&v16,    g_v16);
    cudaGetSymbolAddress((void**)&op,     g_op);
    cudaGetSymbolAddress((void**)&ml,     g_ml);

    cudaFuncSetAttribute(gemm_kv_f16, cudaFuncAttributeMaxDynamicSharedMemorySize,
                         KV_SMEM);
    cudaFuncSetAttribute(gemm_proj, cudaFuncAttributeMaxDynamicSharedMemorySize,
                         KV_SMEM);
    cudaFuncSetAttribute(attn_f16, cudaFuncAttributeMaxDynamicSharedMemorySize,
                         ATTN_SMEM);

    // fused prep + vis pack
    prep_all<<<4096, 256>>>(Wk, Wv, Wq, Wo, lang, w16, wqT, woT, lang16);
    prep_vis16<<<(int)(((long)B_ * (C_ / 2) * S_) / 256), 256>>>(vis, v16p);

    // q projection (fp16 mma) -> f32 q, then validated repack to q16
    gemm_proj<<<dim3(INNER / 128, (B_ * T_) / 128), 256, KV_SMEM>>>(lang16, wqT, q);
    prep_q16<<<B_ * T_ * INNER / 256, 256>>>(q, q16);

    // fused k+v projection (fp16 tensor cores, cp.async, coalesced K epilogue)
    gemm_kv_f16<<<dim3(S_ / 128, (2 * INNER) / 128, B_), 256, KV_SMEM>>>(w16, v16p, k16, v16);

    // flash attention (tensor cores, split-KV, cp.async) + combine + fp16 repack
    attn_f16<<<dim3(SPLIT, BH_), 128, ATTN_SMEM>>>(q16, k16, v16, op, ml);
    attn_combine<<<BH_, 128>>>(op, ml, ao);
    conv16<<<B_ * T_ * INNER / 256, 256>>>(ao, ao16);

    // output projection (fp16 mma) -> f32 out
    gemm_proj<<<dim3(C_ / 128, (B_ * T_) / 128), 256, KV_SMEM>>>(ao16, woT, out);
}

// round 14
// speedup vs baseline: 1.0060x; 1.0042x over previous
#include <cuda_runtime.h>
#include <cuda_fp16.h>
#include <cstdint>

// Problem constants
#define B_    16
#define T_    64
#define C_    512
#define S_    4096
#define INNER 512
#define DIMH  64
#define NHEAD 8
#define BH_   (B_ * NHEAD)
#define SPLIT 4
#define S_PER (S_ / SPLIT)      // 1024

// Scratch (device globals; no allocations allowed)
__device__ float    g_q    [B_ * T_ * INNER];             // q projection f32
__device__ float    g_ao   [B_ * T_ * INNER];             // attention out f32
__device__ __half   g_w16  [2 * INNER * C_];              // concat(Wk,Wv) fp16
__device__ __half   g_lang16[B_ * T_ * C_];               // lang fp16 [1024][512]
__device__ __half   g_ao16 [B_ * T_ * INNER];             // attention out fp16
__device__ uint32_t g_wqT  [(C_ / 2) * INNER];            // Wq^T pair-packed [256][512]
__device__ uint32_t g_woT  [(INNER / 2) * C_];            // Wo^T pair-packed [256][512]
__device__ uint32_t g_v16p [(long)B_ * (C_ / 2) * S_];    // vis fp16 pair-packed
__device__ __half   g_q16  [BH_ * T_ * DIMH];             // q fp16 (bh,t,d), pre-scaled
__device__ __half   g_k16  [(long)BH_ * S_ * DIMH];       // K fp16 s-major (bh,s,d)
__device__ __half   g_v16  [(long)BH_ * DIMH * S_];       // V fp16 d-major (bh,d,s)
__device__ float    g_op   [(long)SPLIT * BH_ * T_ * DIMH]; // partial O
__device__ float    g_ml   [SPLIT * BH_ * T_ * 2];        // partial (m,l)

// pack two fp32 -> one .f16x2 register (lo = first arg)
__device__ __forceinline__ uint32_t f2h2(float lo, float hi) {
    uint32_t r;
    asm("cvt.rn.f16x2.f32 %0, %1, %2;" : "=r"(r) : "f"(hi), "f"(lo));
    return r;
}

__device__ __forceinline__ uint32_t smem_u32(const void* p) {
    uint32_t a;
    asm("{ .reg .u64 t; cvta.to.shared.u64 t, %1; cvt.u32.u64 %0, t; }" : "=r"(a) : "l"(p));
    return a;
}

// ---------------------------------------------------------------------------
__global__ void conv16(const float* __restrict__ src, __half* __restrict__ dst)
{
    const int i = blockIdx.x * 256 + threadIdx.x;
    dst[i] = __float2half_rn(src[i]);
}

// fused prep: w16 concat (blocks 0..1023), Wq^T pack (1024..1535),
// Wo^T pack (1536..2047), lang conv (2048..4095)
__global__ void prep_all(const float* __restrict__ Wk, const float* __restrict__ Wv,
                         const float* __restrict__ Wq, const float* __restrict__ Wo,
                         const float* __restrict__ lang,
                         __half* __restrict__ w16, uint32_t* __restrict__ wqT,
                         uint32_t* __restrict__ woT, __half* __restrict__ lang16)
{
    const int blk = blockIdx.x;
    if (blk < 1024) {
        const int i = blk * 256 + threadIdx.x;
        w16[i]              = __float2half_rn(Wk[i]);
        w16[INNER * C_ + i] = __float2half_rn(Wv[i]);
    } else if (blk < 1536) {
        const int idx = (blk - 1024) * 256 + threadIdx.x;   // k2*512 + n
        const int n  = idx & 511;
        const int k2 = idx >> 9;
        const float* s = Wq + n * 512 + 2 * k2;
        wqT[idx] = f2h2(s[0], s[1]);
    } else if (blk < 2048) {
        const int idx = (blk - 1536) * 256 + threadIdx.x;
        const int n  = idx & 511;
        const int k2 = idx >> 9;
        const float* s = Wo + n * 512 + 2 * k2;
        woT[idx] = f2h2(s[0], s[1]);
    } else {
        const int i = (blk - 2048) * 256 + threadIdx.x;
        lang16[i] = __float2half_rn(lang[i]);
    }
}

__global__ void prep_vis16(const float* __restrict__ vis, uint32_t* __restrict__ vp)
{
    const long i  = (long)blockIdx.x * 256 + threadIdx.x;
    const long s  = i & (S_ - 1);
    const long c2 = (i >> 12) & 255;
    const long b  = i >> 20;
    const float* src = vis + (((b * C_) + 2 * c2) << 12) + s;
    vp[i] = f2h2(src[0], src[S_]);
}

// q f32 (B,T,inner) -> q16 (bh,t,d), scaled by 0.125   [validated]
__global__ void prep_q16(const float* __restrict__ q, __half* __restrict__ q16)
{
    const int i = blockIdx.x * 256 + threadIdx.x;   // 0 .. 524287
    const int d = i & 63;
    const int h = (i >> 6) & 7;
    const int t = (i >> 9) & 63;
    const int b = i >> 15;
    q16[(((b * 8 + h) * T_) + t) * DIMH + d] = __float2half_rn(q[i] * 0.125f);
}

// ---------------------------------------------------------------------------
// shared tile sizes (kv kernel + its clone)
#define NSTAGE   4
#define A_ST_U32 (128 * 20)
#define B_ST_U32 (16 * 136)
#define KV_SMEM  (NSTAGE * (A_ST_U32 + B_ST_U32) * 4)   // 75776 bytes

// ---------------------------------------------------------------------------
// Projection GEMM: Cf[1024][512] = A16[1024][512] @ (packed B)[512][512]
// Verbatim clone of gemm_kv_f16 mainloop with N=512 and f32 epilogue.  [validated]
// ---------------------------------------------------------------------------
__global__ __launch_bounds__(256)
void gemm_proj(const __half* __restrict__ A16,      // [1024][512]
               const uint32_t* __restrict__ Bp,     // [256][512] pairs k2-major
               float* __restrict__ Cf)              // [1024][512]
{
    extern __shared__ uint32_t smdyn[];
    uint32_t (*As)[128][20]  = (uint32_t(*)[128][20])smdyn;
    uint32_t (*Bs)[16][136]  = (uint32_t(*)[16][136])(smdyn + NSTAGE * A_ST_U32);

    const int m0 = blockIdx.y * 128;
    const int n0 = blockIdx.x * 128;
    const uint32_t* Ap = (const uint32_t*)A16;               // pair view [1024][256]

    const int tid  = threadIdx.x;
    const int warp = tid >> 5;
    const int lane = tid & 31;
    const int wm   = (warp >> 1) * 32;
    const int wn   = (warp & 1) * 64;
    const int g    = lane >> 2;
    const int tg   = lane & 3;

    float acc[2][8][4];
    #pragma unroll
    for (int mt = 0; mt < 2; mt++)
        #pragma unroll
        for (int nt = 0; nt < 8; nt++)
            #pragma unroll
            for (int i = 0; i < 4; i++)
                acc[mt][nt][i] = 0.f;

    auto issue = [&](int ch, int st) {
        const int kc2 = ch * 16;
        #pragma unroll
        for (int t = 0; t < 2; t++) {
            const int idx = tid + t * 256;
            const int r = idx >> 2, p4 = (idx & 3) * 4;
            const uint32_t* src = &Ap[(long)(m0 + r) * (C_ / 2) + kc2 + p4];
            asm volatile("cp.async.cg.shared.global [%0], [%1], 16;"
                         :: "r"(smem_u32(&As[st][r][p4])), "l"(src));
        }
        #pragma unroll
        for (int t = 0; t < 2; t++) {
            const int idx = tid + t * 256;
            const int r = idx >> 5, c4 = (idx & 31) * 4;
            const uint32_t* src = &Bp[(long)(kc2 + r) * 512 + n0 + c4];
            asm volatile("cp.async.cg.shared.global [%0], [%1], 16;"
                         :: "r"(smem_u32(&Bs[st][r][c4])), "l"(src));
        }
        asm volatile("cp.async.commit_group;" ::: "memory");
    };

    issue(0, 0); issue(1, 1); issue(2, 2);

    const int NCH = C_ / 32;   // 16
    for (int ch = 0; ch < NCH; ++ch) {
        const int st = ch & (NSTAGE - 1);
        asm volatile("cp.async.wait_group 2;" ::: "memory");
        __syncthreads();

        #pragma unroll
        for (int ks = 0; ks < 2; ks++) {
            const int kb = ks * 8;
            uint32_t bf[8][2];
            #pragma unroll
            for (int nt = 0; nt < 8; nt++) {
                bf[nt][0] = Bs[st][kb + tg]    [wn + nt * 8 + g];
                bf[nt][1] = Bs[st][kb + tg + 4][wn + nt * 8 + g];
            }
            #pragma unroll
            for (int mt = 0; mt < 2; mt++) {
                const int mi = wm + mt * 16 + g;
                uint32_t a0 = As[st][mi]    [kb + tg];
                uint32_t a1 = As[st][mi + 8][kb + tg];
                uint32_t a2 = As[st][mi]    [kb + tg + 4];
                uint32_t a3 = As[st][mi + 8][kb + tg + 4];
                #pragma unroll
                for (int nt = 0; nt < 8; nt++) {
                    asm volatile(
                        "mma.sync.aligned.m16n8k16.row.col.f32.f16.f16.f32 "
                        "{%0,%1,%2,%3}, {%4,%5,%6,%7}, {%8,%9}, {%0,%1,%2,%3};"
                        : "+f"(acc[mt][nt][0]), "+f"(acc[mt][nt][1]),
                          "+f"(acc[mt][nt][2]), "+f"(acc[mt][nt][3])
                        : "r"(a0), "r"(a1), "r"(a2), "r"(a3),
                          "r"(bf[nt][0]), "r"(bf[nt][1]));
                }
            }
        }

        if (ch + NSTAGE - 1 < NCH)
            issue(ch + NSTAGE - 1, (ch + NSTAGE - 1) & (NSTAGE - 1));
    }

    #pragma unroll
    for (int mt = 0; mt < 2; mt++) {
        const int rA = m0 + wm + mt * 16 + g;
        const int rB = rA + 8;
        #pragma unroll
        for (int nt = 0; nt < 8; nt++) {
            const int col = n0 + wn + nt * 8 + 2 * tg;
            *(float2*)&Cf[(long)rA * 512 + col] = make_float2(acc[mt][nt][0], acc[mt][nt][1]);
            *(float2*)&Cf[(long)rB * 512 + col] = make_float2(acc[mt][nt][2], acc[mt][nt][3]);
        }
    }
}

// ---------------------------------------------------------------------------
// Fused k/v projection, fp16 mma, 4-stage cp.async. Mainloop identical to the
// validated R8/R10/R12 kernel. NEW: K epilogue stages accumulators through a
// smem tile (128 m x 130-stride s, halves) and emits fully coalesced 128B row
// writes (was: 2-byte scattered stores with ~16x sector inflation).
// ---------------------------------------------------------------------------
#define KT_STRIDE 130

__global__ __launch_bounds__(256)
void gemm_kv_f16(const __half* __restrict__ A16,      // [1024][512]
                 const uint32_t* __restrict__ Bp,     // [16][256][4096] pairs
                 __half* __restrict__ gk,             // (bh,s,d)
                 __half* __restrict__ gv)             // (bh,d,s)
{
    extern __shared__ uint32_t smdyn[];
    uint32_t (*As)[128][20]  = (uint32_t(*)[128][20])smdyn;
    uint32_t (*Bs)[16][136]  = (uint32_t(*)[16][136])(smdyn + NSTAGE * A_ST_U32);

    const int b  = blockIdx.z;
    const int m0 = blockIdx.y * 128;
    const int n0 = blockIdx.x * 128;
    const uint32_t* Ap = (const uint32_t*)A16;
    const uint32_t* Bb = Bp + (long)b * (C_ / 2) * S_;

    const int tid  = threadIdx.x;
    const int warp = tid >> 5;
    const int lane = tid & 31;
    const int wm   = (warp >> 1) * 32;
    const int wn   = (warp & 1) * 64;
    const int g    = lane >> 2;
    const int tg   = lane & 3;

    float acc[2][8][4];
    #pragma unroll
    for (int mt = 0; mt < 2; mt++)
        #pragma unroll
        for (int nt = 0; nt < 8; nt++)
            #pragma unroll
            for (int i = 0; i < 4; i++)
                acc[mt][nt][i] = 0.f;

    auto issue = [&](int ch, int st) {
        const int kc2 = ch * 16;
        #pragma unroll
        for (int t = 0; t < 2; t++) {
            const int idx = tid + t * 256;
            const int r = idx >> 2, p4 = (idx & 3) * 4;
            const uint32_t* src = &Ap[(long)(m0 + r) * (C_ / 2) + kc2 + p4];
            asm volatile("cp.async.cg.shared.global [%0], [%1], 16;"
                         :: "r"(smem_u32(&As[st][r][p4])), "l"(src));
        }
        #pragma unroll
        for (int t = 0; t < 2; t++) {
            const int idx = tid + t * 256;
            const int r = idx >> 5, c4 = (idx & 31) * 4;
            const uint32_t* src = &Bb[(long)(kc2 + r) * S_ + n0 + c4];
            asm volatile("cp.async.cg.shared.global [%0], [%1], 16;"
                         :: "r"(smem_u32(&Bs[st][r][c4])), "l"(src));
        }
        asm volatile("cp.async.commit_group;" ::: "memory");
    };

    issue(0, 0); issue(1, 1); issue(2, 2);

    const int NCH = C_ / 32;   // 16
    for (int ch = 0; ch < NCH; ++ch) {
        const int st = ch & (NSTAGE - 1);
        asm volatile("cp.async.wait_group 2;" ::: "memory");
        __syncthreads();

        #pragma unroll
        for (int ks = 0; ks < 2; ks++) {
            const int kb = ks * 8;
            uint32_t bf[8][2];
            #pragma unroll
            for (int nt = 0; nt < 8; nt++) {
                bf[nt][0] = Bs[st][kb + tg]    [wn + nt * 8 + g];
                bf[nt][1] = Bs[st][kb + tg + 4][wn + nt * 8 + g];
            }
            #pragma unroll
            for (int mt = 0; mt < 2; mt++) {
                const int mi = wm + mt * 16 + g;
                uint32_t a0 = As[st][mi]    [kb + tg];
                uint32_t a1 = As[st][mi + 8][kb + tg];
                uint32_t a2 = As[st][mi]    [kb + tg + 4];
                uint32_t a3 = As[st][mi + 8][kb + tg + 4];
                #pragma unroll
                for (int nt = 0; nt < 8; nt++) {
                    asm volatile(
                        "mma.sync.aligned.m16n8k16.row.col.f32.f16.f16.f32 "
                        "{%0,%1,%2,%3}, {%4,%5,%6,%7}, {%8,%9}, {%0,%1,%2,%3};"
                        : "+f"(acc[mt][nt][0]), "+f"(acc[mt][nt][1]),
                          "+f"(acc[mt][nt][2]), "+f"(acc[mt][nt][3])
                        : "r"(a0), "r"(a1), "r"(a2), "r"(a3),
                          "r"(bf[nt][0]), "r"(bf[nt][1]));
                }
            }
        }

        if (ch + NSTAGE - 1 < NCH)
            issue(ch + NSTAGE - 1, (ch + NSTAGE - 1) & (NSTAGE - 1));
    }

    if (m0 < 512) {
        // K epilogue: accumulators -> smem tile [m][s] -> coalesced (bh,s,d) rows
        __half* tile = (__half*)smdyn;   // 128 x KT_STRIDE halves (33 KB)
        __syncthreads();                 // all mma fragment reads of smem done
        #pragma unroll
        for (int mt = 0; mt < 2; mt++) {
            const int lmA = wm + mt * 16 + g;
            const int lmB = lmA + 8;
            #pragma unroll
            for (int nt = 0; nt < 8; nt++) {
                const int lc = wn + nt * 8 + 2 * tg;
                tile[lmA * KT_STRIDE + lc]     = __float2half_rn(acc[mt][nt][0]);
                tile[lmA * KT_STRIDE + lc + 1] = __float2half_rn(acc[mt][nt][1]);
                tile[lmB * KT_STRIDE + lc]     = __float2half_rn(acc[mt][nt][2]);
                tile[lmB * KT_STRIDE + lc + 1] = __float2half_rn(acc[mt][nt][3]);
            }
        }
        __syncthreads();
        // 256 rows = 2 heads x 128 s; one warp-row = 32 lanes x 4B = 128B store
        #pragma unroll
        for (int it = 0; it < 32; it++) {
            const int row = warp * 32 + it;
            const int hh  = row >> 7;          // 0 or 1
            const int sl  = row & 127;         // local s
            const int h   = (m0 >> 6) + hh;
            const __half lo = tile[(hh * 64 + 2 * lane)     * KT_STRIDE + sl];
            const __half hi = tile[(hh * 64 + 2 * lane + 1) * KT_STRIDE + sl];
            __half2 v; v.x = lo; v.y = hi;
            *(__half2*)(gk + ((long)(b * 8 + h) * S_ + n0 + sl) * DIMH + 2 * lane) = v;
        }
    } else {
        // V epilogue (unchanged, half2 contiguous-ish)
        #pragma unroll
        for (int mt = 0; mt < 2; mt++) {
            const int mA = m0 + wm + mt * 16 + g;
            const int mB = mA + 8;
            #pragma unroll
            for (int nt = 0; nt < 8; nt++) {
                const int col = n0 + wn + nt * 8 + 2 * tg;
                const int m2A = mA - 512, m2B = mB - 512;
                const int hA = m2A >> 6, dA = m2A & 63;
                const int hB = m2B >> 6, dB = m2B & 63;
                *(uint32_t*)(gv + ((long)(b * 8 + hA) * DIMH + dA) * S_ + col) =
                    f2h2(acc[mt][nt][0], acc[mt][nt][1]);
                *(uint32_t*)(gv + ((long)(b * 8 + hB) * DIMH + dB) * S_ + col) =
                    f2h2(acc[mt][nt][2], acc[mt][nt][3]);
            }
        }
    }
}

// ---------------------------------------------------------------------------
// Tensor-core flash attention, split-KV, double-buffered cp.async staging.
// [validated R12]
// ---------------------------------------------------------------------------
#define KS_STRIDE 72     // halves per K/Q smem row
#define VS_STRIDE 136    // halves per V smem row
#define QS_HALVES (T_ * KS_STRIDE)          // 4608
#define KS_HALVES (128 * KS_STRIDE)         // 9216
#define VS_HALVES (DIMH * VS_STRIDE)        // 8704
#define ATTN_SMEM ((QS_HALVES + 2 * KS_HALVES + 2 * VS_HALVES) * 2)   // 80896 B

__global__ __launch_bounds__(128)
void attn_f16(const __half* __restrict__ q16, const __half* __restrict__ k16,
              const __half* __restrict__ v16, float* __restrict__ opart,
              float* __restrict__ ml)
{
    extern __shared__ __half smd[];
    __half* Qs  = smd;
    __half* Ksb = smd + QS_HALVES;
    __half* Vsb = smd + QS_HALVES + 2 * KS_HALVES;

    const int sp  = blockIdx.x;
    const int bh  = blockIdx.y;
    const int tid = threadIdx.x;
    const int warp = tid >> 5;
    const int lane = tid & 31;
    const int g   = lane >> 2;
    const int tg  = lane & 3;
    const int wm  = warp * 16;

    const __half* kb = k16 + ((long)bh * S_ + sp * S_PER) * DIMH;
    const __half* vb = v16 + (long)bh * DIMH * S_ + sp * S_PER;
    const int NT = S_PER / 128;   // 8

    auto issue_tile = [&](int tile, int buf) {
        __half* Ks = Ksb + buf * KS_HALVES;
        __half* Vs = Vsb + buf * VS_HALVES;
        #pragma unroll
        for (int t = 0; t < 8; t++) {
            const int idx = tid + t * 128;
            const int r = idx >> 3, c8 = idx & 7;
            const __half* src = &kb[(long)(tile * 128 + r) * DIMH + c8 * 8];
            asm volatile("cp.async.cg.shared.global [%0], [%1], 16;"
                         :: "r"(smem_u32(&Ks[r * KS_STRIDE + c8 * 8])), "l"(src));
        }
        #pragma unroll
        for (int t = 0; t < 8; t++) {
            const int idx = tid + t * 128;
            const int r = idx >> 4, c16 = idx & 15;
            const __half* src = &vb[(long)r * S_ + tile * 128 + c16 * 8];
            asm volatile("cp.async.cg.shared.global [%0], [%1], 16;"
                         :: "r"(smem_u32(&Vs[r * VS_STRIDE + c16 * 8])), "l"(src));
        }
        asm volatile("cp.async.commit_group;" ::: "memory");
    };

    issue_tile(0, 0);
    issue_tile(1, 1);

    const __half* qb = q16 + (long)bh * T_ * DIMH;
    #pragma unroll
    for (int t = 0; t < 4; t++) {
        const int idx = tid + t * 128;
        const int r = idx >> 3, c8 = idx & 7;
        *(uint4*)&Qs[r * KS_STRIDE + c8 * 8] = *(const uint4*)&qb[r * DIMH + c8 * 8];
    }
    __syncthreads();

    uint32_t aq[4][4];
    #pragma unroll
    for (int ks = 0; ks < 4; ks++) {
        aq[ks][0] = *(const uint32_t*)&Qs[(wm + g)     * KS_STRIDE + ks * 16 + 2 * tg];
        aq[ks][1] = *(const uint32_t*)&Qs[(wm + g + 8) * KS_STRIDE + ks * 16 + 2 * tg];
        aq[ks][2] = *(const uint32_t*)&Qs[(wm + g)     * KS_STRIDE + ks * 16 + 2 * tg + 8];
        aq[ks][3] = *(const uint32_t*)&Qs[(wm + g + 8) * KS_STRIDE + ks * 16 + 2 * tg + 8];
    }

    float accO[8][4];
    #pragma unroll
    for (int nt = 0; nt < 8; nt++)
        #pragma unroll
        for (int i = 0; i < 4; i++) accO[nt][i] = 0.f;
    float m0r = -1e30f, m1r = -1e30f, l0 = 0.f, l1 = 0.f;

    for (int tile = 0; tile < NT; tile++) {
        const int buf = tile & 1;
        __half* Ks = Ksb + buf * KS_HALVES;
        __half* Vs = Vsb + buf * VS_HALVES;

        if (tile + 1 < NT)
            asm volatile("cp.async.wait_group 1;" ::: "memory");
        else
            asm volatile("cp.async.wait_group 0;" ::: "memory");
        __syncthreads();

        float accS[16][4];
        #pragma unroll
        for (int nt = 0; nt < 16; nt++)
            #pragma unroll
            for (int i = 0; i < 4; i++) accS[nt][i] = 0.f;

        #pragma unroll
        for (int ks = 0; ks < 4; ks++) {
            #pragma unroll
            for (int nt = 0; nt < 16; nt++) {
                uint32_t b0 = *(const uint32_t*)&Ks[(nt * 8 + g) * KS_STRIDE + ks * 16 + 2 * tg];
                uint32_t b1 = *(const uint32_t*)&Ks[(nt * 8 + g) * KS_STRIDE + ks * 16 + 2 * tg + 8];
                asm volatile(
                    "mma.sync.aligned.m16n8k16.row.col.f32.f16.f16.f32 "
                    "{%0,%1,%2,%3}, {%4,%5,%6,%7}, {%8,%9}, {%0,%1,%2,%3};"
                    : "+f"(accS[nt][0]), "+f"(accS[nt][1]),
                      "+f"(accS[nt][2]), "+f"(accS[nt][3])
                    : "r"(aq[ks][0]), "r"(aq[ks][1]), "r"(aq[ks][2]), "r"(aq[ks][3]),
                      "r"(b0), "r"(b1));
            }
        }

        float mx0 = -1e30f, mx1 = -1e30f;
        #pragma unroll
        for (int nt = 0; nt < 16; nt++) {
            mx0 = fmaxf(mx0, fmaxf(accS[nt][0], accS[nt][1]));
            mx1 = fmaxf(mx1, fmaxf(accS[nt][2], accS[nt][3]));
        }
        mx0 = fmaxf(mx0, __shfl_xor_sync(0xffffffffu, mx0, 1));
        mx0 = fmaxf(mx0, __shfl_xor_sync(0xffffffffu, mx0, 2));
        mx1 = fmaxf(mx1, __shfl_xor_sync(0xffffffffu, mx1, 1));
        mx1 = fmaxf(mx1, __shfl_xor_sync(0xffffffffu, mx1, 2));

        const float mn0 = fmaxf(m0r, mx0);
        const float mn1 = fmaxf(m1r, mx1);
        const float cr0 = __expf(m0r - mn0);
        const float cr1 = __expf(m1r - mn1);
        m0r = mn0; m1r = mn1;

        float s0 = 0.f, s1 = 0.f;
        #pragma unroll
        for (int nt = 0; nt < 16; nt++) {
            accS[nt][0] = __expf(accS[nt][0] - mn0);
            accS[nt][1] = __expf(accS[nt][1] - mn0);
            accS[nt][2] = __expf(accS[nt][2] - mn1);
            accS[nt][3] = __expf(accS[nt][3] - mn1);
            s0 += accS[nt][0] + accS[nt][1];
            s1 += accS[nt][2] + accS[nt][3];
        }
        s0 += __shfl_xor_sync(0xffffffffu, s0, 1);
        s0 += __shfl_xor_sync(0xffffffffu, s0, 2);
        s1 += __shfl_xor_sync(0xffffffffu, s1, 1);
        s1 += __shfl_xor_sync(0xffffffffu, s1, 2);
        l0 = l0 * cr0 + s0;
        l1 = l1 * cr1 + s1;

        #pragma unroll
        for (int nt = 0; nt < 8; nt++) {
            accO[nt][0] *= cr0; accO[nt][1] *= cr0;
            accO[nt][2] *= cr1; accO[nt][3] *= cr1;
        }

        uint32_t ap[8][4];
        #pragma unroll
        for (int ks = 0; ks < 8; ks++) {
            ap[ks][0] = f2h2(accS[2*ks][0],   accS[2*ks][1]);
            ap[ks][1] = f2h2(accS[2*ks][2],   accS[2*ks][3]);
            ap[ks][2] = f2h2(accS[2*ks+1][0], accS[2*ks+1][1]);
            ap[ks][3] = f2h2(accS[2*ks+1][2], accS[2*ks+1][3]);
        }

        #pragma unroll
        for (int ks = 0; ks < 8; ks++) {
            #pragma unroll
            for (int nt = 0; nt < 8; nt++) {
                uint32_t b0 = *(const uint32_t*)&Vs[(nt * 8 + g) * VS_STRIDE + ks * 16 + 2 * tg];
                uint32_t b1 = *(const uint32_t*)&Vs[(nt * 8 + g) * VS_STRIDE + ks * 16 + 2 * tg + 8];
                asm volatile(
                    "mma.sync.aligned.m16n8k16.row.col.f32.f16.f16.f32 "
                    "{%0,%1,%2,%3}, {%4,%5,%6,%7}, {%8,%9}, {%0,%1,%2,%3};"
                    : "+f"(accO[nt][0]), "+f"(accO[nt][1]),
                      "+f"(accO[nt][2]), "+f"(accO[nt][3])
                    : "r"(ap[ks][0]), "r"(ap[ks][1]), "r"(ap[ks][2]), "r"(ap[ks][3]),
                      "r"(b0), "r"(b1));
            }
        }

        __syncthreads();
        if (tile + 2 < NT)
            issue_tile(tile + 2, buf);
    }

    float* op = opart + ((long)(sp * BH_ + bh) * T_) * DIMH;
    const int rA = wm + g, rB = wm + g + 8;
    #pragma unroll
    for (int nt = 0; nt < 8; nt++) {
        const int col = nt * 8 + 2 * tg;
        *(float2*)&op[rA * DIMH + col] = make_float2(accO[nt][0], accO[nt][1]);
        *(float2*)&op[rB * DIMH + col] = make_float2(accO[nt][2], accO[nt][3]);
    }
    if (tg == 0) {
        float* mlp = ml + ((long)(sp * BH_ + bh) * T_) * 2;
        mlp[rA * 2] = m0r; mlp[rA * 2 + 1] = l0;
        mlp[rB * 2] = m1r; mlp[rB * 2 + 1] = l1;
    }
}

// ---------------------------------------------------------------------------
// split-KV combine -> g_ao (B,T,inner) f32   [validated]
// ---------------------------------------------------------------------------
__global__ void attn_combine(const float* __restrict__ opart,
                             const float* __restrict__ ml, float* __restrict__ ao)
{
    const int bh  = blockIdx.x;
    const int b   = bh >> 3;
    const int h   = bh & 7;
    const int tid = threadIdx.x;       // 128
    const int t   = tid >> 1;
    const int d0  = (tid & 1) * 32;

    float m[SPLIT], l[SPLIT];
    float M = -1e30f;
    #pragma unroll
    for (int i = 0; i < SPLIT; i++) {
        m[i] = ml[((long)(i * BH_ + bh) * T_ + t) * 2];
        l[i] = ml[((long)(i * BH_ + bh) * T_ + t) * 2 + 1];
        M = fmaxf(M, m[i]);
    }
    float w[SPLIT], L = 0.f;
    #pragma unroll
    for (int i = 0; i < SPLIT; i++) {
        w[i] = __expf(m[i] - M);
        L += w[i] * l[i];
    }
    const float inv = 1.f / L;

    float* dst = ao + ((long)(b * T_ + t)) * INNER + h * DIMH + d0;
    #pragma unroll
    for (int d = 0; d < 32; d++) {
        float o = 0.f;
        #pragma unroll
        for (int i = 0; i < SPLIT; i++)
            o += w[i] * opart[((long)(i * BH_ + bh) * T_ + t) * DIMH + d0 + d];
        dst[d] = o * inv;
    }
}

// ---------------------------------------------------------------------------
extern "C" void kernel_launch(void* const* d_in, const int* in_sizes, int n_in,
                              void* d_out, int out_size)
{
    const float* vis  = (const float*)d_in[0];
    const float* lang = (const float*)d_in[1];
    // d_in[2] = mask (unused)
    const float* Wq   = (const float*)d_in[3];
    const float* Wk   = (const float*)d_in[4];
    const float* Wv   = (const float*)d_in[5];
    const float* Wo   = (const float*)d_in[6];
    float* out = (float*)d_out;

    float *q, *ao, *op, *ml;
    __half *w16, *lang16, *ao16, *q16, *k16, *v16;
    uint32_t *v16p, *wqT, *woT;
    cudaGetSymbolAddress((void**)&q,      g_q);
    cudaGetSymbolAddress((void**)&ao,     g_ao);
    cudaGetSymbolAddress((void**)&w16,    g_w16);
    cudaGetSymbolAddress((void**)&lang16, g_lang16);
    cudaGetSymbolAddress((void**)&ao16,   g_ao16);
    cudaGetSymbolAddress((void**)&wqT,    g_wqT);
    cudaGetSymbolAddress((void**)&woT,    g_woT);
    cudaGetSymbolAddress((void**)&v16p,   g_v16p);
    cudaGetSymbolAddress((void**)&q16,    g_q16);
    cudaGetSymbolAddress((void**)&k16,    g_k16);
    cudaGetSymbolAddress((void**)&v16,    g_v16);
    cudaGetSymbolAddress((void**)&op,     g_op);
    cudaGetSymbolAddress((void**)&ml,     g_ml);

    cudaFuncSetAttribute(gemm_kv_f16, cudaFuncAttributeMaxDynamicSharedMemorySize,
                         KV_SMEM);
    cudaFuncSetAttribute(gemm_proj, cudaFuncAttributeMaxDynamicSharedMemorySize,
                         KV_SMEM);
    cudaFuncSetAttribute(attn_f16, cudaFuncAttributeMaxDynamicSharedMemorySize,
                         ATTN_SMEM);

    // fused prep + vis pack
    prep_all<<<4096, 256>>>(Wk, Wv, Wq, Wo, lang, w16, wqT, woT, lang16);
    prep_vis16<<<(int)(((long)B_ * (C_ / 2) * S_) / 256), 256>>>(vis, v16p);

    // q projection (fp16 mma) -> f32 q, then validated repack to q16
    gemm_proj<<<dim3(INNER / 128, (B_ * T_) / 128), 256, KV_SMEM>>>(lang16, wqT, q);
    prep_q16<<<B_ * T_ * INNER / 256, 256>>>(q, q16);

    // fused k+v projection (fp16 tensor cores, cp.async, coalesced K epilogue)
    gemm_kv_f16<<<dim3(S_ / 128, (2 * INNER) / 128, B_), 256, KV_SMEM>>>(w16, v16p, k16, v16);

    // flash attention (tensor cores, split-KV, cp.async) + combine + fp16 repack
    attn_f16<<<dim3(SPLIT, BH_), 128, ATTN_SMEM>>>(q16, k16, v16, op, ml);
    attn_combine<<<BH_, 128>>>(op, ml, ao);
    conv16<<<B_ * T_ * INNER / 256, 256>>>(ao, ao16);

    // output projection (fp16 mma) -> f32 out
    gemm_proj<<<dim3(C_ / 128, (B_ * T_) / 128), 256, KV_SMEM>>>(ao16, woT, out);
}